// round 16
// baseline (speedup 1.0000x reference)
#include <cuda_runtime.h>
#include <cuda_bf16.h>
#include <math.h>
#include <stdint.h>

#define C_DIM 768
#define NSEQ  4096
#define HEADS 12
#define HD    64
#define BM    64               // q rows per CTA (flash)
#define BN    64               // keys per tile (flash)
#define NTILES (NSEQ / BN)
#define ROWB  72               // flash padded row length (bf16) = 144 B
#define STAGE_BYTES 36864      // flash: 4 arrays x 64 x 144 B
#define FLASH_SMEM  (2 * STAGE_BYTES)

#define GROWP 40               // gemm padded k-extent (80 B rows)
// big-tile gemm staging: Ah 256x80 | Al | Bh 128x80 | Bl
#define GB_AH 0u
#define GB_AL 20480u
#define GB_BH 40960u
#define GB_BL 51200u
#define GB_STG 61440
#define GB_SMEM (3 * GB_STG)

// q scale: 8 (reference quirk q/D^-0.5) x log2(e) -> softmax via exp2
#define QSCALE 11.541560327111707f

// pre-split operand planes (bf16 hi/lo)
__device__ __nv_bfloat16 g_xh[(size_t)NSEQ * C_DIM],  g_xl[(size_t)NSEQ * C_DIM];
__device__ __nv_bfloat16 g_wqh[(size_t)3 * C_DIM * C_DIM], g_wql[(size_t)3 * C_DIM * C_DIM];
__device__ __nv_bfloat16 g_wph[(size_t)C_DIM * C_DIM], g_wpl[(size_t)C_DIM * C_DIM];
__device__ __nv_bfloat16 g_atth[(size_t)NSEQ * C_DIM], g_attl[(size_t)NSEQ * C_DIM];
// Q planes [token][C_DIM] (pre-scaled by QSCALE); K [h][key][d]; V^T [h][d][key]
__device__ __nv_bfloat16 g_qh[(size_t)NSEQ * C_DIM],  g_ql[(size_t)NSEQ * C_DIM];
__device__ __nv_bfloat16 g_kh[(size_t)HEADS * NSEQ * HD];
__device__ __nv_bfloat16 g_kl[(size_t)HEADS * NSEQ * HD];
__device__ __nv_bfloat16 g_vth[(size_t)HEADS * HD * NSEQ];
__device__ __nv_bfloat16 g_vtl[(size_t)HEADS * HD * NSEQ];

// ---------------------------------------------------------------------------
// helpers
// ---------------------------------------------------------------------------
__device__ __forceinline__ void mma16816(float c[4], const uint32_t a[4],
                                         uint32_t b0, uint32_t b1) {
    asm("mma.sync.aligned.m16n8k16.row.col.f32.bf16.bf16.f32 "
        "{%0,%1,%2,%3}, {%4,%5,%6,%7}, {%8,%9}, {%0,%1,%2,%3};"
        : "+f"(c[0]), "+f"(c[1]), "+f"(c[2]), "+f"(c[3])
        : "r"(a[0]), "r"(a[1]), "r"(a[2]), "r"(a[3]), "r"(b0), "r"(b1));
}
__device__ __forceinline__ void ldsm4(uint32_t& r0, uint32_t& r1,
                                      uint32_t& r2, uint32_t& r3, uint32_t addr) {
    asm volatile("ldmatrix.sync.aligned.m8n8.x4.shared.b16 {%0,%1,%2,%3}, [%4];"
                 : "=r"(r0), "=r"(r1), "=r"(r2), "=r"(r3) : "r"(addr));
}
__device__ __forceinline__ uint32_t pack_bf16(float lo, float hi) {
    uint32_t r;
    asm("cvt.rn.bf16x2.f32 %0, %1, %2;" : "=r"(r) : "f"(hi), "f"(lo));
    return r;
}
__device__ __forceinline__ void split1(float v, float& h, float& l) {
    h = __bfloat162float(__float2bfloat16(v));
    l = v - h;
}
__device__ __forceinline__ void split8_store(const float v[8],
                                             void* ph, void* pl) {
    uint32_t H[4], L[4];
    #pragma unroll
    for (int i = 0; i < 4; i++) {
        float h0, l0, h1, l1;
        split1(v[2 * i],     h0, l0);
        split1(v[2 * i + 1], h1, l1);
        H[i] = pack_bf16(h0, h1);
        L[i] = pack_bf16(l0, l1);
    }
    *(uint4*)ph = make_uint4(H[0], H[1], H[2], H[3]);
    *(uint4*)pl = make_uint4(L[0], L[1], L[2], L[3]);
}
__device__ __forceinline__ uint32_t smem_u32(const void* p) {
    uint32_t a;
    asm("{ .reg .u64 t; cvta.to.shared.u64 t, %1; cvt.u32.u64 %0, t; }"
        : "=r"(a) : "l"(p));
    return a;
}
__device__ __forceinline__ void cp16(uint32_t dst, const void* src) {
    asm volatile("cp.async.cg.shared.global [%0], [%1], 16;"
                 :: "r"(dst), "l"(src));
}
#define CP_COMMIT() asm volatile("cp.async.commit_group;" ::: "memory")
#define CP_WAIT1()  asm volatile("cp.async.wait_group 1;" ::: "memory")
#define CP_WAIT0()  asm volatile("cp.async.wait_group 0;" ::: "memory")

// ===========================================================================
// fp32 -> bf16 hi/lo plane split
// ===========================================================================
__global__ __launch_bounds__(256)
void split_f32(const float* __restrict__ src, __nv_bfloat16* __restrict__ dh,
               __nv_bfloat16* __restrict__ dl, int n)
{
    int i = (blockIdx.x * 256 + threadIdx.x) * 8;
    if (i >= n) return;
    float4 a = *(const float4*)(src + i);
    float4 b = *(const float4*)(src + i + 4);
    float v[8] = {a.x, a.y, a.z, a.w, b.x, b.y, b.z, b.w};
    split8_store(v, dh + i, dl + i);
}

// ===========================================================================
// Big-tile pre-split GEMM NT: 256x128 CTA, 512 threads, 1 CTA/SM,
// 3-stage cp.async pipeline.
// MODE 0: plain fp32 C + bias.
// MODE 1: fused QKV epilogue — writes bf16 hi/lo planes directly:
//   cols [0,768):    Q  -> g_qh/g_ql [token][C_DIM], value scaled by QSCALE
//   cols [768,1536): K  -> g_kh/g_kl [h][key][d]
//   cols [1536,2304):V  -> g_vth/g_vtl [h][d][key] (transposed)
// Each CTA's 128-col span lies wholly in one region (768 = 6*128).
// ===========================================================================
template<int MODE>
__global__ __launch_bounds__(512, 1)
void gemm_big(const __nv_bfloat16* __restrict__ Ahg,
              const __nv_bfloat16* __restrict__ Alg,
              const __nv_bfloat16* __restrict__ Bhg,
              const __nv_bfloat16* __restrict__ Blg,
              const float* __restrict__ bias, float* __restrict__ C,
              int M, int N, int K)
{
    extern __shared__ __align__(16) uint8_t gsm[];
    const uint32_t sbase = smem_u32(gsm);

    const int tid = threadIdx.x, wid = tid >> 5, lane = tid & 31;
    const int g = lane >> 2, t2 = (lane & 3) * 2;
    const int wr = wid >> 1, wc = wid & 1;           // 8 x 2 warp grid
    const int m0 = blockIdx.y * 256, n0 = blockIdx.x * 128;

    const uint32_t aRow = (uint32_t)((wr * 32 + (lane & 15)) * 80 + (lane >> 4) * 16);
    const uint32_t bRow = (uint32_t)((wc * 64 + (lane >> 4) * 8 + (lane & 7)) * 80
                                     + ((lane >> 3) & 1) * 16);

    const __nv_bfloat16* srcs[4] = {
        Ahg + (size_t)m0 * K, Alg + (size_t)m0 * K,
        Bhg + (size_t)n0 * K, Blg + (size_t)n0 * K };
    const uint32_t offs[4] = { GB_AH, GB_AL, GB_BH, GB_BL };

    auto issue = [&](int kb, int st) {
        const uint32_t sb = sbase + st * GB_STG;
        #pragma unroll
        for (int i = 0; i < 6; i++) {
            int e = tid + i * 512;
            int arr, rem;
            if (e < 1024)      { arr = 0; rem = e; }
            else if (e < 2048) { arr = 1; rem = e - 1024; }
            else if (e < 2560) { arr = 2; rem = e - 2048; }
            else               { arr = 3; rem = e - 2560; }
            int row = rem >> 2, c = rem & 3;
            cp16(sb + offs[arr] + row * 80 + c * 16,
                 srcs[arr] + (size_t)row * K + kb * 32 + c * 8);
        }
    };

    float acc[2][8][4];
    #pragma unroll
    for (int mt = 0; mt < 2; mt++)
        #pragma unroll
        for (int nt = 0; nt < 8; nt++)
            #pragma unroll
            for (int r = 0; r < 4; r++) acc[mt][nt][r] = 0.f;

    const int nkb = K / 32;           // 24
    issue(0, 0); CP_COMMIT();
    issue(1, 1); CP_COMMIT();

    for (int kb = 0; kb < nkb; kb++) {
        if (kb + 1 < nkb) { CP_WAIT1(); } else { CP_WAIT0(); }
        __syncthreads();

        const uint32_t sb = sbase + (kb % 3) * GB_STG;

        #pragma unroll
        for (int kc = 0; kc < 2; kc++) {
            const uint32_t kcb = kc * 32;
            uint32_t aH[2][4], aL[2][4];
            #pragma unroll
            for (int mt = 0; mt < 2; mt++) {
                ldsm4(aH[mt][0], aH[mt][1], aH[mt][2], aH[mt][3],
                      sb + GB_AH + mt * (16 * 80) + aRow + kcb);
                ldsm4(aL[mt][0], aL[mt][1], aL[mt][2], aL[mt][3],
                      sb + GB_AL + mt * (16 * 80) + aRow + kcb);
            }
            #pragma unroll
            for (int np = 0; np < 4; np++) {
                uint32_t bh[4], bl[4];
                ldsm4(bh[0], bh[1], bh[2], bh[3],
                      sb + GB_BH + np * (16 * 80) + bRow + kcb);
                ldsm4(bl[0], bl[1], bl[2], bl[3],
                      sb + GB_BL + np * (16 * 80) + bRow + kcb);
                mma16816(acc[0][2*np],   aH[0], bh[0], bh[1]);
                mma16816(acc[1][2*np],   aH[1], bh[0], bh[1]);
                mma16816(acc[0][2*np+1], aH[0], bh[2], bh[3]);
                mma16816(acc[1][2*np+1], aH[1], bh[2], bh[3]);
                mma16816(acc[0][2*np],   aH[0], bl[0], bl[1]);
                mma16816(acc[1][2*np],   aH[1], bl[0], bl[1]);
                mma16816(acc[0][2*np+1], aH[0], bl[2], bl[3]);
                mma16816(acc[1][2*np+1], aH[1], bl[2], bl[3]);
                mma16816(acc[0][2*np],   aL[0], bh[0], bh[1]);
                mma16816(acc[1][2*np],   aL[1], bh[0], bh[1]);
                mma16816(acc[0][2*np+1], aL[0], bh[2], bh[3]);
                mma16816(acc[1][2*np+1], aL[1], bh[2], bh[3]);
            }
        }
        __syncthreads();
        if (kb + 2 < nkb) { issue(kb + 2, (kb + 2) % 3); CP_COMMIT(); }
    }

    // ---- epilogue ----
    #pragma unroll
    for (int nt = 0; nt < 8; nt++) {
        const int cn = n0 + wc * 64 + nt * 8 + t2;
        const float2 bb = make_float2(bias[cn], bias[cn + 1]);
        #pragma unroll
        for (int mt = 0; mt < 2; mt++) {
            const int rm = m0 + wr * 32 + mt * 16 + g;
            float p0 = acc[mt][nt][0] + bb.x, p1 = acc[mt][nt][1] + bb.y;  // row rm
            float p2 = acc[mt][nt][2] + bb.x, p3 = acc[mt][nt][3] + bb.y;  // row rm+8
            if (MODE == 0) {
                *(float2*)(C + (size_t)rm * N + cn)       = make_float2(p0, p1);
                *(float2*)(C + (size_t)(rm + 8) * N + cn) = make_float2(p2, p3);
            } else {
                if (cn < C_DIM) {
                    // Q plane: scale by QSCALE, split, [token][C_DIM]
                    float h0, l0, h1, l1;
                    split1(p0 * QSCALE, h0, l0); split1(p1 * QSCALE, h1, l1);
                    *(uint32_t*)(g_qh + (size_t)rm * C_DIM + cn) = pack_bf16(h0, h1);
                    *(uint32_t*)(g_ql + (size_t)rm * C_DIM + cn) = pack_bf16(l0, l1);
                    split1(p2 * QSCALE, h0, l0); split1(p3 * QSCALE, h1, l1);
                    *(uint32_t*)(g_qh + (size_t)(rm + 8) * C_DIM + cn) = pack_bf16(h0, h1);
                    *(uint32_t*)(g_ql + (size_t)(rm + 8) * C_DIM + cn) = pack_bf16(l0, l1);
                } else if (cn < 2 * C_DIM) {
                    // K plane: [h][key][d]
                    int hh = cn - C_DIM;
                    int head = hh >> 6, d = hh & 63;
                    size_t base = (size_t)head * NSEQ * HD + (size_t)rm * HD + d;
                    float h0, l0, h1, l1;
                    split1(p0, h0, l0); split1(p1, h1, l1);
                    *(uint32_t*)(g_kh + base) = pack_bf16(h0, h1);
                    *(uint32_t*)(g_kl + base) = pack_bf16(l0, l1);
                    split1(p2, h0, l0); split1(p3, h1, l1);
                    *(uint32_t*)(g_kh + base + 8 * HD) = pack_bf16(h0, h1);
                    *(uint32_t*)(g_kl + base + 8 * HD) = pack_bf16(l0, l1);
                } else {
                    // V plane transposed: [h][d][key]
                    int hh = cn - 2 * C_DIM;
                    int head = hh >> 6, d = hh & 63;
                    size_t base = (size_t)head * HD * NSEQ + (size_t)d * NSEQ;
                    float h0, l0, h1, l1;
                    split1(p0, h0, l0); split1(p1, h1, l1);
                    g_vth[base + rm] = __float2bfloat16_rn(h0);
                    g_vtl[base + rm] = __float2bfloat16_rn(l0);
                    g_vth[base + NSEQ + rm] = __float2bfloat16_rn(h1);
                    g_vtl[base + NSEQ + rm] = __float2bfloat16_rn(l1);
                    split1(p2, h0, l0); split1(p3, h1, l1);
                    g_vth[base + rm + 8] = __float2bfloat16_rn(h0);
                    g_vtl[base + rm + 8] = __float2bfloat16_rn(l0);
                    g_vth[base + NSEQ + rm + 8] = __float2bfloat16_rn(h1);
                    g_vtl[base + NSEQ + rm + 8] = __float2bfloat16_rn(l1);
                }
            }
        }
    }
}

// ===========================================================================
// Flash attention: BM=64, 128 threads, 3 CTAs/SM, LDSM, cp.async double
// buffer, split-bf16 mma, exp2 softmax, no online max. Q read pre-split.
// ===========================================================================
__global__ __launch_bounds__(128, 3)
void flash_mma()
{
    extern __shared__ __align__(16) uint8_t smem[];

    const int tid = threadIdx.x, wid = tid >> 5, lane = tid & 31;
    const int h = blockIdx.y, q0 = blockIdx.x * BM;
    const int g = lane >> 2, t2 = (lane & 3) * 2;
    const uint32_t sbase = smem_u32(smem);

    const uint32_t bRow = (uint32_t)(((lane >> 4) * 8 + (lane & 7)) * 144
                                     + ((lane >> 3) & 1) * 16);

    // ---- stage Q from pre-split planes (pure cp.async, 8 chunks per thread) ----
    {
        const __nv_bfloat16* qh = g_qh;
        const __nv_bfloat16* ql = g_ql;
        #pragma unroll
        for (int i = 0; i < 4; i++) {
            int e = tid + i * 128;                // 0..511: 64 rows x 8 chunks
            int r = e >> 3, c16 = e & 7;
            uint32_t soff = (uint32_t)(r * 144 + c16 * 16);
            size_t goff = (size_t)(q0 + r) * C_DIM + h * HD + c16 * 8;
            cp16(sbase + soff,        qh + goff);
            cp16(sbase + 9216 + soff, ql + goff);
        }
        CP_COMMIT();
        CP_WAIT0();
    }
    __syncthreads();

    uint32_t aQh[4][4], aQl[4][4];
    {
        const __nv_bfloat16* Qh = (const __nv_bfloat16*)(smem);
        const __nv_bfloat16* Ql = (const __nv_bfloat16*)(smem + 9216);
        const int r0 = wid * 16;
        #pragma unroll
        for (int kc = 0; kc < 4; kc++) {
            int col = kc * 16 + t2;
            aQh[kc][0] = *(const uint32_t*)(Qh + (r0 + g)     * ROWB + col);
            aQh[kc][1] = *(const uint32_t*)(Qh + (r0 + g + 8) * ROWB + col);
            aQh[kc][2] = *(const uint32_t*)(Qh + (r0 + g)     * ROWB + col + 8);
            aQh[kc][3] = *(const uint32_t*)(Qh + (r0 + g + 8) * ROWB + col + 8);
            aQl[kc][0] = *(const uint32_t*)(Ql + (r0 + g)     * ROWB + col);
            aQl[kc][1] = *(const uint32_t*)(Ql + (r0 + g + 8) * ROWB + col);
            aQl[kc][2] = *(const uint32_t*)(Ql + (r0 + g)     * ROWB + col + 8);
            aQl[kc][3] = *(const uint32_t*)(Ql + (r0 + g + 8) * ROWB + col + 8);
        }
    }
    __syncthreads();

    const __nv_bfloat16* khg  = g_kh  + (size_t)h * NSEQ * HD;
    const __nv_bfloat16* klg  = g_kl  + (size_t)h * NSEQ * HD;
    const __nv_bfloat16* vthg = g_vth + (size_t)h * HD * NSEQ;
    const __nv_bfloat16* vtlg = g_vtl + (size_t)h * HD * NSEQ;

    auto issue_tile = [&](int t, int st) {
        const uint32_t sb = sbase + st * STAGE_BYTES;
        #pragma unroll
        for (int i = 0; i < 4; i++) {
            int e = tid + i * 128;
            int row = e >> 3, c16 = e & 7;
            uint32_t soff = (uint32_t)(row * 144 + c16 * 16);
            size_t kg = ((size_t)(t * BN + row)) * HD + c16 * 8;
            cp16(sb + soff,         khg + kg);
            cp16(sb + 9216 + soff,  klg + kg);
            size_t vg = (size_t)row * NSEQ + t * BN + c16 * 8;
            cp16(sb + 18432 + soff, vthg + vg);
            cp16(sb + 27648 + soff, vtlg + vg);
        }
    };

    float O[8][4];
    #pragma unroll
    for (int n = 0; n < 8; n++)
        #pragma unroll
        for (int r = 0; r < 4; r++) O[n][r] = 0.f;
    float lsum0 = 0.f, lsum1 = 0.f;

    issue_tile(0, 0);
    CP_COMMIT();

    for (int t = 0; t < NTILES; t++) {
        if (t < NTILES - 1) {
            issue_tile(t + 1, (t + 1) & 1);
            CP_COMMIT();
            CP_WAIT1();
        } else {
            CP_WAIT0();
        }
        __syncthreads();

        const uint32_t sb = sbase + (t & 1) * STAGE_BYTES;

        float S[8][4];
        #pragma unroll
        for (int n = 0; n < 8; n++)
            #pragma unroll
            for (int r = 0; r < 4; r++) S[n][r] = 0.f;

        #pragma unroll
        for (int kc = 0; kc < 4; kc++) {
            const uint32_t kcb = kc * 32;
            #pragma unroll
            for (int np = 0; np < 4; np++) {
                uint32_t bh[4], bl[4];
                ldsm4(bh[0], bh[1], bh[2], bh[3],
                      sb + np * (16 * 144) + bRow + kcb);
                ldsm4(bl[0], bl[1], bl[2], bl[3],
                      sb + 9216 + np * (16 * 144) + bRow + kcb);
                mma16816(S[2*np],   aQh[kc], bh[0], bh[1]);
                mma16816(S[2*np+1], aQh[kc], bh[2], bh[3]);
                mma16816(S[2*np],   aQh[kc], bl[0], bl[1]);
                mma16816(S[2*np+1], aQh[kc], bl[2], bl[3]);
                mma16816(S[2*np],   aQl[kc], bh[0], bh[1]);
                mma16816(S[2*np+1], aQl[kc], bh[2], bh[3]);
            }
        }

        #pragma unroll
        for (int kc = 0; kc < 4; kc++) {
            uint32_t aPh[4], aPl[4];
            {
                const int n = 2 * kc;
                float e0 = exp2f(S[n][0]), e1 = exp2f(S[n][1]);
                float e2 = exp2f(S[n][2]), e3 = exp2f(S[n][3]);
                lsum0 += e0 + e1; lsum1 += e2 + e3;
                float h0, l0, h1, l1;
                split1(e0, h0, l0); split1(e1, h1, l1);
                aPh[0] = pack_bf16(h0, h1); aPl[0] = pack_bf16(l0, l1);
                split1(e2, h0, l0); split1(e3, h1, l1);
                aPh[1] = pack_bf16(h0, h1); aPl[1] = pack_bf16(l0, l1);
            }
            {
                const int n = 2 * kc + 1;
                float e0 = exp2f(S[n][0]), e1 = exp2f(S[n][1]);
                float e2 = exp2f(S[n][2]), e3 = exp2f(S[n][3]);
                lsum0 += e0 + e1; lsum1 += e2 + e3;
                float h0, l0, h1, l1;
                split1(e0, h0, l0); split1(e1, h1, l1);
                aPh[2] = pack_bf16(h0, h1); aPl[2] = pack_bf16(l0, l1);
                split1(e2, h0, l0); split1(e3, h1, l1);
                aPh[3] = pack_bf16(h0, h1); aPl[3] = pack_bf16(l0, l1);
            }
            const uint32_t kcb = kc * 32;
            #pragma unroll
            for (int np = 0; np < 4; np++) {
                uint32_t bh[4], bl[4];
                ldsm4(bh[0], bh[1], bh[2], bh[3],
                      sb + 18432 + np * (16 * 144) + bRow + kcb);
                ldsm4(bl[0], bl[1], bl[2], bl[3],
                      sb + 27648 + np * (16 * 144) + bRow + kcb);
                mma16816(O[2*np],   aPh, bh[0], bh[1]);
                mma16816(O[2*np+1], aPh, bh[2], bh[3]);
                mma16816(O[2*np],   aPh, bl[0], bl[1]);
                mma16816(O[2*np+1], aPh, bl[2], bl[3]);
                mma16816(O[2*np],   aPl, bh[0], bh[1]);
                mma16816(O[2*np+1], aPl, bh[2], bh[3]);
            }
        }
        __syncthreads();
    }

    lsum0 += __shfl_xor_sync(0xffffffffu, lsum0, 1);
    lsum0 += __shfl_xor_sync(0xffffffffu, lsum0, 2);
    lsum1 += __shfl_xor_sync(0xffffffffu, lsum1, 1);
    lsum1 += __shfl_xor_sync(0xffffffffu, lsum1, 2);
    const float inv0 = 1.f / lsum0, inv1 = 1.f / lsum1;

    const int row0 = q0 + wid * 16 + g, row1 = row0 + 8;
    const size_t base0 = (size_t)row0 * C_DIM + h * HD;
    const size_t base1 = (size_t)row1 * C_DIM + h * HD;
    #pragma unroll
    for (int n = 0; n < 8; n++) {
        float v0 = O[n][0] * inv0, v1 = O[n][1] * inv0;
        float v2 = O[n][2] * inv1, v3 = O[n][3] * inv1;
        float h0, l0, h1, l1;
        split1(v0, h0, l0); split1(v1, h1, l1);
        *(uint32_t*)(g_atth + base0 + n * 8 + t2) = pack_bf16(h0, h1);
        *(uint32_t*)(g_attl + base0 + n * 8 + t2) = pack_bf16(l0, l1);
        split1(v2, h0, l0); split1(v3, h1, l1);
        *(uint32_t*)(g_atth + base1 + n * 8 + t2) = pack_bf16(h0, h1);
        *(uint32_t*)(g_attl + base1 + n * 8 + t2) = pack_bf16(l0, l1);
    }
}

// ---------------------------------------------------------------------------
extern "C" void kernel_launch(void* const* d_in, const int* in_sizes, int n_in,
                              void* d_out, int out_size)
{
    (void)in_sizes; (void)n_in; (void)out_size;
    const float* x      = (const float*)d_in[0];
    const float* qkv_w  = (const float*)d_in[1];
    const float* qkv_b  = (const float*)d_in[2];
    const float* proj_w = (const float*)d_in[3];
    const float* proj_b = (const float*)d_in[4];
    float* out = (float*)d_out;

    __nv_bfloat16 *xh, *xl, *wqh, *wql, *wph, *wpl, *ath, *atl;
    cudaGetSymbolAddress((void**)&xh,  g_xh);
    cudaGetSymbolAddress((void**)&xl,  g_xl);
    cudaGetSymbolAddress((void**)&wqh, g_wqh);
    cudaGetSymbolAddress((void**)&wql, g_wql);
    cudaGetSymbolAddress((void**)&wph, g_wph);
    cudaGetSymbolAddress((void**)&wpl, g_wpl);
    cudaGetSymbolAddress((void**)&ath, g_atth);
    cudaGetSymbolAddress((void**)&atl, g_attl);

    static bool attr_set = false;
    if (!attr_set) {
        cudaFuncSetAttribute(flash_mma,
                             cudaFuncAttributeMaxDynamicSharedMemorySize,
                             FLASH_SMEM);
        cudaFuncSetAttribute(gemm_big<0>,
                             cudaFuncAttributeMaxDynamicSharedMemorySize,
                             GB_SMEM);
        cudaFuncSetAttribute(gemm_big<1>,
                             cudaFuncAttributeMaxDynamicSharedMemorySize,
                             GB_SMEM);
        attr_set = true;
    }

    // 0) pre-split GEMM operands
    {
        int nx = NSEQ * C_DIM;
        split_f32<<<nx / 2048, 256>>>(x, xh, xl, nx);
        int nw = 3 * C_DIM * C_DIM;
        split_f32<<<nw / 2048, 256>>>(qkv_w, wqh, wql, nw);
        int np = C_DIM * C_DIM;
        split_f32<<<np / 2048, 256>>>(proj_w, wph, wpl, np);
    }

    // 1) QKV projection with fused split epilogue (Q/K/V planes direct)
    dim3 g1((3 * C_DIM) / 128, NSEQ / 256);
    gemm_big<1><<<g1, 512, GB_SMEM>>>(xh, xl, wqh, wql, qkv_b, nullptr,
                                      NSEQ, 3 * C_DIM, C_DIM);

    // 2) flash attention (BM=64, 128 threads, 3 CTAs/SM)
    dim3 g2(NSEQ / BM, HEADS);
    flash_mma<<<g2, 128, FLASH_SMEM>>>();

    // 3) output projection: 256x128 tiles
    dim3 g3(C_DIM / 128, NSEQ / 256);
    gemm_big<0><<<g3, 512, GB_SMEM>>>(ath, atl, wph, wpl, proj_b, out,
                                      NSEQ, C_DIM, C_DIM);
}